// round 1
// baseline (speedup 1.0000x reference)
#include <cuda_runtime.h>

#define BATCH 8
#define LEN   2048
#define EMB   512
#define NQ    8

// scratch for rot = x @ rotation : (8, 2048, 8) fp32 = 512 KB
__device__ float g_rot[BATCH * LEN * NQ];

// ---------------------------------------------------------------------------
// Kernel 1: rot[b,l,q] = sum_e x[b,l,e] * rotation[e,q]
// Block = 256 threads (8 warps), each warp computes 4 rows -> 32 rows/block.
// rotation staged transposed in smem: srotT[q][e], conflict-free (lane = e mod 32).
// ---------------------------------------------------------------------------
__global__ __launch_bounds__(256) void rot_kernel(const float* __restrict__ x,
                                                  const float* __restrict__ rotation)
{
    __shared__ float srotT[NQ * EMB];   // [q][e]
    const int tid = threadIdx.x;

    for (int idx = tid; idx < EMB * NQ; idx += 256) {
        int e = idx >> 3;
        int q = idx & 7;
        srotT[q * EMB + e] = rotation[idx];
    }
    __syncthreads();

    const int warp = tid >> 5;
    const int lane = tid & 31;
    const int row0 = (blockIdx.x * 8 + warp) * 4;   // 4 rows per warp

    float acc[4][NQ];
#pragma unroll
    for (int r = 0; r < 4; r++)
#pragma unroll
        for (int q = 0; q < NQ; q++) acc[r][q] = 0.0f;

#pragma unroll 4
    for (int k = 0; k < EMB / 32; k++) {
        const int e = lane + 32 * k;
        float xv[4];
#pragma unroll
        for (int r = 0; r < 4; r++)
            xv[r] = x[(size_t)(row0 + r) * EMB + e];
#pragma unroll
        for (int q = 0; q < NQ; q++) {
            const float rq = srotT[q * EMB + e];
#pragma unroll
            for (int r = 0; r < 4; r++)
                acc[r][q] = fmaf(xv[r], rq, acc[r][q]);
        }
    }

    // reduce across lanes
#pragma unroll
    for (int r = 0; r < 4; r++)
#pragma unroll
        for (int q = 0; q < NQ; q++) {
#pragma unroll
            for (int off = 16; off > 0; off >>= 1)
                acc[r][q] += __shfl_xor_sync(0xffffffffu, acc[r][q], off);
        }

    if (lane == 0) {
#pragma unroll
        for (int r = 0; r < 4; r++)
#pragma unroll
            for (int q = 0; q < NQ; q++)
                g_rot[(size_t)(row0 + r) * NQ + q] = acc[r][q];
    }
}

// ---------------------------------------------------------------------------
// Kernel 2: scores[b,i,j] = sigmoid(rot_i . rot_j) / sum_j sigmoid(.)
// Grid: (LEN/8, BATCH). Block: 512 threads.
// Each block owns 8 full rows (i0..i0+7). Thread t owns columns j in [4t,4t+4).
// rot_j tile (4 rows x 8 q) lives in registers, reused for all 8 i-rows.
// Sigmoid values stay in registers; one block-reduce gives each row sum; one
// coalesced float4 store per (i, thread) writes the normalized result.
// ---------------------------------------------------------------------------
__global__ __launch_bounds__(512, 1) void attn_kernel(float* __restrict__ out)
{
    const int b   = blockIdx.y;
    const int i0  = blockIdx.x * 8;
    const int tid = threadIdx.x;
    const int warp = tid >> 5;
    const int lane = tid & 31;

    __shared__ float  s_qi[8 * NQ];     // the 8 rot_i rows
    __shared__ float  s_part[8][16];    // per-warp partial sums
    __shared__ float  s_inv[8];

    if (tid < 64)
        s_qi[tid] = g_rot[((size_t)b * LEN + i0) * NQ + tid];

    // load this thread's 4 rot_j rows (32 floats) into registers
    const float4* rj = reinterpret_cast<const float4*>(
        &g_rot[((size_t)b * LEN + tid * 4) * NQ]);
    float4 rja[8];
#pragma unroll
    for (int u = 0; u < 8; u++) rja[u] = rj[u];

    __syncthreads();

    float val[8][4];

#pragma unroll
    for (int i = 0; i < 8; i++) {
        const float4 q0 = reinterpret_cast<const float4*>(s_qi)[i * 2 + 0];
        const float4 q1 = reinterpret_cast<const float4*>(s_qi)[i * 2 + 1];
        float psum = 0.0f;
#pragma unroll
        for (int r = 0; r < 4; r++) {
            const float4 a = rja[r * 2 + 0];
            const float4 c = rja[r * 2 + 1];
            float s = a.x * q0.x;
            s = fmaf(a.y, q0.y, s);
            s = fmaf(a.z, q0.z, s);
            s = fmaf(a.w, q0.w, s);
            s = fmaf(c.x, q1.x, s);
            s = fmaf(c.y, q1.y, s);
            s = fmaf(c.z, q1.z, s);
            s = fmaf(c.w, q1.w, s);
            // sigmoid: saturates to exactly 0 / 1 for |s| large, matching fp32 ref
            const float p = __fdividef(1.0f, 1.0f + __expf(-s));
            val[i][r] = p;
            psum += p;
        }
#pragma unroll
        for (int off = 16; off > 0; off >>= 1)
            psum += __shfl_xor_sync(0xffffffffu, psum, off);
        if (lane == 0) s_part[i][warp] = psum;
    }

    __syncthreads();

    if (tid < 8) {
        float s = 0.0f;
#pragma unroll
        for (int w = 0; w < 16; w++) s += s_part[tid][w];
        s_inv[tid] = 1.0f / s;
    }
    __syncthreads();

#pragma unroll
    for (int i = 0; i < 8; i++) {
        const float inv = s_inv[i];
        float4 o;
        o.x = val[i][0] * inv;
        o.y = val[i][1] * inv;
        o.z = val[i][2] * inv;
        o.w = val[i][3] * inv;
        reinterpret_cast<float4*>(
            &out[((size_t)(b * LEN + i0 + i)) * LEN + tid * 4])[0] = o;
    }
}

extern "C" void kernel_launch(void* const* d_in, const int* in_sizes, int n_in,
                              void* d_out, int out_size)
{
    const float* x        = (const float*)d_in[0];   // (8, 2048, 512)
    const float* rotation = (const float*)d_in[1];   // (512, 8)
    // d_in[2] = entangle, unused in forward
    float* out = (float*)d_out;                      // (8, 2048, 2048)

    // Kernel 1: 16384 rows / 32 rows per block = 512 blocks
    rot_kernel<<<512, 256>>>(x, rotation);

    // Kernel 2: 8 rows per block, full 2048 cols -> grid (256, 8)
    dim3 grid(LEN / 8, BATCH);
    attn_kernel<<<grid, 512>>>(out);
}